// round 1
// baseline (speedup 1.0000x reference)
#include <cuda_runtime.h>
#include <float.h>

// Problem constants (fixed by reference)
#define B_ 2
#define T_ 5
#define C_ 3
#define H_ 96
#define W_ 96
#define WS_ 9
#define WT_ 1
#define PS_ 5
#define PSD_ 7
#define K_ 10
#define S0_ 4
#define NH_ (H_ / S0_)              // 24
#define NW_ (W_ / S0_)              // 24
#define Q_ (T_ * NH_ * NW_)         // 2880
#define L_ ((2 * WT_ + 1) * WS_ * WS_)  // 243
#define LSELF_ (WT_ * WS_ * WS_ + (WS_ / 2) * WS_ + (WS_ / 2))  // 121
#define NDR_ ((K_ - 1) * C_ * PSD_ * PSD_)  // 9*147 = 1323

__device__ float g_acc;

__device__ __forceinline__ int refl(int i, int n) {
    i = i < 0 ? -i : i;
    return i >= n ? 2 * (n - 1) - i : i;
}
__device__ __forceinline__ int clampi(int i, int lo, int hi) {
    return min(max(i, lo), hi);
}

__global__ void zero_k() { g_acc = 0.0f; }

__global__ __launch_bounds__(256) void dnls_main_k(
    const float* __restrict__ noisy,
    const float* __restrict__ deno)
{
    const int blk = blockIdx.x;
    const int b = blk / Q_;
    const int q = blk % Q_;
    const int qt = q / (NH_ * NW_);
    const int qr = q % (NH_ * NW_);
    const int qh = (qr / NW_) * S0_;
    const int qw = (qr % NW_) * S0_;
    const int tid = threadIdx.x;

    __shared__ float qp[C_ * PS_ * PS_];   // 75 query patch values
    __shared__ float dsm[256];             // 243 distances (padded)
    __shared__ int   sel[K_];
    __shared__ float red[8];

    const float* nb = noisy + (size_t)b * T_ * C_ * H_ * W_;
    const float* db = deno  + (size_t)b * T_ * C_ * H_ * W_;

    // Stage query 5x5 patch (reflect padding)
    if (tid < C_ * PS_ * PS_) {
        int c  = tid / (PS_ * PS_);
        int rr = tid % (PS_ * PS_);
        int dy = rr / PS_ - PS_ / 2;
        int dx = rr % PS_ - PS_ / 2;
        qp[tid] = nb[(qt * C_ + c) * H_ * W_ +
                     refl(qh + dy, H_) * W_ + refl(qw + dx, W_)];
    }
    if (tid >= L_) dsm[tid] = FLT_MAX;
    __syncthreads();

    // ---- Phase 1: 243 candidate distances (one thread each) ----
    if (tid < L_) {
        int dti = tid / (WS_ * WS_);
        int rem = tid % (WS_ * WS_);
        int dhi = rem / WS_;
        int dwi = rem % WS_;
        int ct = clampi(qt + dti - WT_,     0, T_ - 1);
        int ch = clampi(qh + dhi - WS_ / 2, 0, H_ - 1);
        int cw = clampi(qw + dwi - WS_ / 2, 0, W_ - 1);

        int cols[PS_];
        #pragma unroll
        for (int dx = 0; dx < PS_; dx++) cols[dx] = refl(cw + dx - PS_ / 2, W_);

        float acc = 0.0f;
        #pragma unroll
        for (int c = 0; c < C_; c++) {
            #pragma unroll
            for (int dy = 0; dy < PS_; dy++) {
                const float* rowp = nb + (ct * C_ + c) * H_ * W_ +
                                    refl(ch + dy - PS_ / 2, H_) * W_;
                #pragma unroll
                for (int dx = 0; dx < PS_; dx++) {
                    float a = qp[(c * PS_ + dy) * PS_ + dx];
                    float v = __ldg(&rowp[cols[dx]]);
                    float df = a - v;
                    acc = fmaf(df, df, acc);
                }
            }
        }
        dsm[tid] = (tid == LSELF_) ? -1.0f : acc;
    }
    __syncthreads();

    // ---- Phase 2: K=10 smallest, lowest-index tie-break (warp 0) ----
    if (tid < 32) {
        for (int k = 0; k < K_; k++) {
            float bd = FLT_MAX;
            int   bi = 1 << 20;
            for (int i = tid; i < L_; i += 32) {
                float v = dsm[i];
                if (v < bd) { bd = v; bi = i; }  // scan ascending: keeps lowest idx
            }
            #pragma unroll
            for (int off = 16; off; off >>= 1) {
                float od = __shfl_down_sync(0xffffffffu, bd, off);
                int   oi = __shfl_down_sync(0xffffffffu, bi, off);
                if (od < bd || (od == bd && oi < bi)) { bd = od; bi = oi; }
            }
            bd = __shfl_sync(0xffffffffu, bd, 0);
            bi = __shfl_sync(0xffffffffu, bi, 0);
            if (tid == 0) { sel[k] = bi; dsm[bi] = FLT_MAX; }
            __syncwarp();
        }
    }
    __syncthreads();

    // ---- Phase 3: dr over ranks 1..K-1, 3x7x7 patches ----
    float part = 0.0f;
    for (int i = tid; i < NDR_; i += 256) {
        int k = i / (C_ * PSD_ * PSD_) + 1;   // skip self (rank 0)
        int j = i % (C_ * PSD_ * PSD_);
        int l = sel[k];
        int dti = l / (WS_ * WS_);
        int rem = l % (WS_ * WS_);
        int dhi = rem / WS_;
        int dwi = rem % WS_;
        int it = clampi(qt + dti - WT_,     0, T_ - 1);
        int ih = clampi(qh + dhi - WS_ / 2, 0, H_ - 1);
        int iw = clampi(qw + dwi - WS_ / 2, 0, W_ - 1);

        int c  = j / (PSD_ * PSD_);
        int rr = j % (PSD_ * PSD_);
        int dy = rr / PSD_ - PSD_ / 2;
        int dx = rr % PSD_ - PSD_ / 2;

        float pd = __ldg(&db[(qt * C_ + c) * H_ * W_ +
                             refl(qh + dy, H_) * W_ + refl(qw + dx, W_)]);
        float pk = __ldg(&nb[(it * C_ + c) * H_ * W_ +
                             refl(ih + dy, H_) * W_ + refl(iw + dx, W_)]);
        float df = pd - pk;
        part = fmaf(df, df, part);
    }

    // Block reduction
    #pragma unroll
    for (int off = 16; off; off >>= 1)
        part += __shfl_down_sync(0xffffffffu, part, off);
    if ((tid & 31) == 0) red[tid >> 5] = part;
    __syncthreads();
    if (tid == 0) {
        float s = 0.0f;
        #pragma unroll
        for (int w = 0; w < 8; w++) s += red[w];
        atomicAdd(&g_acc, s);
    }
}

__global__ void final_k(float* out) {
    out[0] = g_acc / (float)(B_ * Q_ * (K_ - 1));
}

extern "C" void kernel_launch(void* const* d_in, const int* in_sizes, int n_in,
                              void* d_out, int out_size) {
    const float* noisy = (const float*)d_in[0];
    const float* deno  = (const float*)d_in[1];
    // d_in[2] = curr_epoch (unused by reference computation)
    zero_k<<<1, 1>>>();
    dnls_main_k<<<B_ * Q_, 256>>>(noisy, deno);
    final_k<<<1, 1>>>((float*)d_out);
}

// round 2
// speedup vs baseline: 1.2106x; 1.2106x over previous
#include <cuda_runtime.h>
#include <float.h>

// Problem constants (fixed by reference)
#define B_ 2
#define T_ 5
#define C_ 3
#define H_ 96
#define W_ 96
#define WS_ 9
#define WT_ 1
#define PS_ 5
#define PSD_ 7
#define K_ 10
#define S0_ 4
#define NH_ (H_ / S0_)              // 24
#define NW_ (W_ / S0_)              // 24
#define Q_ (T_ * NH_ * NW_)         // 2880
#define L_ ((2 * WT_ + 1) * WS_ * WS_)  // 243
#define LSELF_ (WT_ * WS_ * WS_ + (WS_ / 2) * WS_ + (WS_ / 2))  // 121
#define NDR_ ((K_ - 1) * C_ * PSD_ * PSD_)  // 1323

// Tile: per (frame-slot, channel) plane of 15 rows x 16 cols (stride 16)
#define TR_ 15
#define TSTR_ 16
#define TPLANE_ (TR_ * TSTR_)       // 240

__device__ float g_part[B_ * Q_];

__device__ __forceinline__ int refl(int i, int n) {
    i = i < 0 ? -i : i;
    return i >= n ? 2 * (n - 1) - i : i;
}
__device__ __forceinline__ int clampi(int i, int lo, int hi) {
    return min(max(i, lo), hi);
}

__global__ __launch_bounds__(256) void dnls_main_k(
    const float* __restrict__ noisy,
    const float* __restrict__ deno)
{
    const int blk = blockIdx.x;
    const int b = blk / Q_;
    const int q = blk % Q_;
    const int qt = q / (NH_ * NW_);
    const int qr = q % (NH_ * NW_);
    const int qh = (qr / NW_) * S0_;
    const int qw = (qr % NW_) * S0_;
    const int tid = threadIdx.x;

    __shared__ float tile[9 * TPLANE_];    // noisy: [dti*3+c][15][16]
    __shared__ float dtile[3 * TPLANE_];   // deno frame qt: [c][15][16]
    __shared__ float dsm[256];
    __shared__ int   sel[K_];
    __shared__ int   selt[K_ - 1], selh[K_ - 1], selw[K_ - 1];
    __shared__ float red[8];

    const float* nb = noisy + (size_t)b * T_ * C_ * H_ * W_;
    const float* db = deno  + (size_t)b * T_ * C_ * H_ * W_;

    // All accesses (reflect for patches, clamp for centers) of raw coords in
    // [qh-7, qh+7] x [qw-7, qw+7] land in [rlo,rhi] x [clo,chi].
    const int rlo = max(0, qh - 7), rhi = min(H_ - 1, qh + 7);
    const int clo = max(0, qw - 7), chi = min(W_ - 1, qw + 7);
    const int Rn = rhi - rlo + 1, Cn = chi - clo + 1;

    // ---- Stage noisy region: 3 frame slots x 3 channels ----
    for (int idx = tid; idx < 9 * TPLANE_; idx += 256) {
        int cc = idx & (TSTR_ - 1);
        int rest = idx >> 4;           // plane*15 + rr
        int rr = rest % TR_;
        int plane = rest / TR_;
        if (rr < Rn && cc < Cn) {
            int dti = plane / 3, c = plane % 3;
            int ft = clampi(qt + dti - WT_, 0, T_ - 1);
            tile[idx] = __ldg(&nb[(ft * C_ + c) * H_ * W_ + (rlo + rr) * W_ + (clo + cc)]);
        }
    }
    // ---- Stage deno region (frame qt, 3 channels) ----
    for (int idx = tid; idx < 3 * TPLANE_; idx += 256) {
        int cc = idx & (TSTR_ - 1);
        int rest = idx >> 4;
        int rr = rest % TR_;
        int c = rest / TR_;
        if (rr < Rn && cc < Cn) {
            dtile[idx] = __ldg(&db[(qt * C_ + c) * H_ * W_ + (rlo + rr) * W_ + (clo + cc)]);
        }
    }
    if (tid >= L_) dsm[tid] = FLT_MAX;
    __syncthreads();

    // ---- Phase 1: 243 candidate distances, all reads from smem ----
    if (tid < L_) {
        int dti = tid / (WS_ * WS_);
        int rem = tid % (WS_ * WS_);
        int dhi = rem / WS_;
        int dwi = rem % WS_;
        int ch = clampi(qh + dhi - WS_ / 2, 0, H_ - 1);
        int cw = clampi(qw + dwi - WS_ / 2, 0, W_ - 1);

        int crow[PS_], ccol[PS_], qrow[PS_], qcol[PS_];
        #pragma unroll
        for (int d = 0; d < PS_; d++) {
            crow[d] = refl(ch + d - PS_ / 2, H_) - rlo;
            ccol[d] = refl(cw + d - PS_ / 2, W_) - clo;
            qrow[d] = refl(qh + d - PS_ / 2, H_) - rlo;
            qcol[d] = refl(qw + d - PS_ / 2, W_) - clo;
        }

        float acc = 0.0f;
        #pragma unroll
        for (int c = 0; c < C_; c++) {
            const float* tc = &tile[(dti * 3 + c) * TPLANE_];
            const float* tq = &tile[(1 * 3 + c) * TPLANE_];   // slot 1 = frame qt
            #pragma unroll
            for (int dy = 0; dy < PS_; dy++) {
                const float* rq = tq + qrow[dy] * TSTR_;
                const float* rc = tc + crow[dy] * TSTR_;
                #pragma unroll
                for (int dx = 0; dx < PS_; dx++) {
                    float df = rq[qcol[dx]] - rc[ccol[dx]];
                    acc = fmaf(df, df, acc);
                }
            }
        }
        dsm[tid] = (tid == LSELF_) ? -1.0f : acc;
    }
    __syncthreads();

    // ---- Phase 2: K smallest, lowest-index tie-break (warp 0) ----
    if (tid < 32) {
        for (int k = 0; k < K_; k++) {
            float bd = FLT_MAX;
            int   bi = 1 << 20;
            for (int i = tid; i < L_; i += 32) {
                float v = dsm[i];
                if (v < bd) { bd = v; bi = i; }
            }
            #pragma unroll
            for (int off = 16; off; off >>= 1) {
                float od = __shfl_down_sync(0xffffffffu, bd, off);
                int   oi = __shfl_down_sync(0xffffffffu, bi, off);
                if (od < bd || (od == bd && oi < bi)) { bd = od; bi = oi; }
            }
            bi = __shfl_sync(0xffffffffu, bi, 0);
            if (tid == 0) { sel[k] = bi; dsm[bi] = FLT_MAX; }
            __syncwarp();
        }
    }
    __syncthreads();

    // Decode coords for ranks 1..K-1
    if (tid < K_ - 1) {
        int l = sel[tid + 1];
        int dti = l / (WS_ * WS_);
        int rem = l % (WS_ * WS_);
        selt[tid] = dti;   // frame slot index
        selh[tid] = clampi(qh + rem / WS_ - WS_ / 2, 0, H_ - 1);
        selw[tid] = clampi(qw + rem % WS_ - WS_ / 2, 0, W_ - 1);
    }
    __syncthreads();

    // ---- Phase 3: dr over ranks 1..9, 3x7x7 patches, all from smem ----
    float part = 0.0f;
    for (int i = tid; i < NDR_; i += 256) {
        int k = i / (C_ * PSD_ * PSD_);           // 0..8
        int j = i % (C_ * PSD_ * PSD_);
        int c  = j / (PSD_ * PSD_);
        int rr = j % (PSD_ * PSD_);
        int dy = rr / PSD_ - PSD_ / 2;
        int dx = rr % PSD_ - PSD_ / 2;

        float pd = dtile[c * TPLANE_ +
                         (refl(qh + dy, H_) - rlo) * TSTR_ +
                         (refl(qw + dx, W_) - clo)];
        float pk = tile[(selt[k] * 3 + c) * TPLANE_ +
                        (refl(selh[k] + dy, H_) - rlo) * TSTR_ +
                        (refl(selw[k] + dx, W_) - clo)];
        float df = pd - pk;
        part = fmaf(df, df, part);
    }

    // ---- Block reduction -> deterministic per-CTA partial ----
    #pragma unroll
    for (int off = 16; off; off >>= 1)
        part += __shfl_down_sync(0xffffffffu, part, off);
    if ((tid & 31) == 0) red[tid >> 5] = part;
    __syncthreads();
    if (tid == 0) {
        float s = 0.0f;
        #pragma unroll
        for (int w = 0; w < 8; w++) s += red[w];
        g_part[blk] = s;
    }
}

__global__ __launch_bounds__(256) void final_k(float* out) {
    __shared__ float red[8];
    const int tid = threadIdx.x;
    float s = 0.0f;
    for (int i = tid; i < B_ * Q_; i += 256) s += g_part[i];
    #pragma unroll
    for (int off = 16; off; off >>= 1)
        s += __shfl_down_sync(0xffffffffu, s, off);
    if ((tid & 31) == 0) red[tid >> 5] = s;
    __syncthreads();
    if (tid == 0) {
        float t = 0.0f;
        #pragma unroll
        for (int w = 0; w < 8; w++) t += red[w];
        out[0] = t * (1.0f / (float)(B_ * Q_ * (K_ - 1)));
    }
}

extern "C" void kernel_launch(void* const* d_in, const int* in_sizes, int n_in,
                              void* d_out, int out_size) {
    const float* noisy = (const float*)d_in[0];
    const float* deno  = (const float*)d_in[1];
    // d_in[2] = curr_epoch (unused by the reference computation)
    dnls_main_k<<<B_ * Q_, 256>>>(noisy, deno);
    final_k<<<1, 256>>>((float*)d_out);
}